// round 1
// baseline (speedup 1.0000x reference)
#include <cuda_runtime.h>
#include <cstdint>
#include <cstddef>

#define NB    4
#define NN    4096
#define DD    512
#define NROWS (NB*NN)      // 16384
#define MAXD  96
#define SEGS  8
#define SEGCAP 32
#define SEGLEN (NN/SEGS)   // 512

// ---------------- scratch (static __device__, no allocs) ----------------
__device__ float          g_bufA[NROWS*DD];            // GEMM output (d-scaled)
__device__ float          g_bufB[NROWS*DD];            // SpMM output (hidden act)
__device__ unsigned int   g_Wt[3*DD*DD];               // tf32-converted weights
__device__ unsigned short g_seg_idx[NROWS*SEGS*SEGCAP];
__device__ int            g_seg_cnt[NROWS*SEGS];
__device__ unsigned short g_idx[NROWS*MAXD];
__device__ int            g_cnt[NROWS];
__device__ float          g_deg[NROWS];                // rsqrt(colsum)

// ---------------- adjacency structure build ----------------
// thread (lane=i within 32-chunk, y=segment s, blockIdx=(i-chunk, b))
// scans column i of adj[b] over j in [s*512,(s+1)*512). Coalesced across lanes.
__global__ void build_seg(const float* __restrict__ adj) {
    int i = blockIdx.x * 32 + threadIdx.x;
    int s = threadIdx.y;
    int b = blockIdx.y;
    int row = b * NN + i;
    unsigned short* out = &g_seg_idx[(size_t)(row * SEGS + s) * SEGCAP];
    const float* colp = adj + (size_t)b * NN * NN + i;
    int j0 = s * SEGLEN;
    int c = 0;
    #pragma unroll 4
    for (int jj = 0; jj < SEGLEN; jj++) {
        int j = j0 + jj;
        float v = colp[(size_t)j * NN];
        if (v != 0.0f) {
            if (c < SEGCAP) out[c] = (unsigned short)j;
            c++;
        }
    }
    g_seg_cnt[row * SEGS + s] = c;
}

__global__ void compact_deg() {
    int row = blockIdx.x * blockDim.x + threadIdx.x;
    if (row >= NROWS) return;
    unsigned short* dst = &g_idx[(size_t)row * MAXD];
    int total = 0;   // true colsum
    int nout = 0;    // entries written
    for (int s = 0; s < SEGS; s++) {
        int c = g_seg_cnt[row * SEGS + s];
        int cc = c < SEGCAP ? c : SEGCAP;
        const unsigned short* src = &g_seg_idx[(size_t)(row * SEGS + s) * SEGCAP];
        for (int k = 0; k < cc; k++) {
            if (nout < MAXD) dst[nout++] = src[k];
        }
        total += c;
    }
    g_cnt[row] = nout;
    g_deg[row] = rsqrtf((float)total);   // total >= 1 (self loop)
}

// ---------------- weight fp32 -> tf32 (round to nearest) ----------------
__global__ void cvt_w(const float* __restrict__ w, int which) {
    int t = blockIdx.x * blockDim.x + threadIdx.x;
    if (t < DD * DD) {
        unsigned int u;
        asm("cvt.rna.tf32.f32 %0, %1;" : "=r"(u) : "f"(w[t]));
        g_Wt[which * DD * DD + t] = u;
    }
}

// ---------------- tf32 tensor-core GEMM ----------------
// C[m,n] = sum_k A[m,k]*W[k,n];  writes g_bufA[m,n] = deg[m]*C[m,n]
// BM=128, BN=128, BK=32; 256 threads (8 warps), warp tile 64x32.
#define BM 128
#define BN 128
#define BK 32
#define ASTRIDE 133
#define BSTRIDE 136

__device__ __forceinline__ void mma_tf32(float* c, const unsigned int* a, const unsigned int* b) {
    asm volatile(
        "mma.sync.aligned.m16n8k8.row.col.f32.tf32.tf32.f32 "
        "{%0,%1,%2,%3}, {%4,%5,%6,%7}, {%8,%9}, {%0,%1,%2,%3};"
        : "+f"(c[0]), "+f"(c[1]), "+f"(c[2]), "+f"(c[3])
        : "r"(a[0]), "r"(a[1]), "r"(a[2]), "r"(a[3]), "r"(b[0]), "r"(b[1]));
}

__global__ __launch_bounds__(256, 2)
void gemm_tf32(const float* __restrict__ Ain_or_null, int wwhich) {
    const float* Ain = Ain_or_null ? Ain_or_null : g_bufB;
    const unsigned int* W = &g_Wt[wwhich * DD * DD];

    __shared__ unsigned int As[BK * ASTRIDE];   // [k][m]
    __shared__ unsigned int Bs[BK * BSTRIDE];   // [k][n]

    const int tid  = threadIdx.x;
    const int lane = tid & 31;
    const int wid  = tid >> 5;
    const int wm   = wid & 1;        // 0..1 -> 64-row half
    const int wn   = wid >> 1;       // 0..3 -> 32-col quarter
    const int g    = lane >> 2;      // 0..7
    const int t    = lane & 3;       // 0..3

    const int nBase = blockIdx.x * BN;
    const int mBase = blockIdx.y * BM;

    float acc[4][4][4];
    #pragma unroll
    for (int mi = 0; mi < 4; mi++)
        #pragma unroll
        for (int ni = 0; ni < 4; ni++)
            #pragma unroll
            for (int q = 0; q < 4; q++) acc[mi][ni][q] = 0.0f;

    for (int k0 = 0; k0 < DD; k0 += BK) {
        if (k0 != 0) __syncthreads();
        // load A tile 128x32 fp32 -> cvt tf32 -> smem [k][m]
        #pragma unroll
        for (int r = 0; r < 4; r++) {
            int idx = tid + r * 256;
            int m  = idx >> 3;
            int kq = (idx & 7) << 2;
            float4 v = *(const float4*)(Ain + (size_t)(mBase + m) * DD + k0 + kq);
            unsigned int u0, u1, u2, u3;
            asm("cvt.rna.tf32.f32 %0, %1;" : "=r"(u0) : "f"(v.x));
            asm("cvt.rna.tf32.f32 %0, %1;" : "=r"(u1) : "f"(v.y));
            asm("cvt.rna.tf32.f32 %0, %1;" : "=r"(u2) : "f"(v.z));
            asm("cvt.rna.tf32.f32 %0, %1;" : "=r"(u3) : "f"(v.w));
            As[(kq + 0) * ASTRIDE + m] = u0;
            As[(kq + 1) * ASTRIDE + m] = u1;
            As[(kq + 2) * ASTRIDE + m] = u2;
            As[(kq + 3) * ASTRIDE + m] = u3;
        }
        // load B tile 32x128 (already tf32) -> smem [k][n]
        #pragma unroll
        for (int r = 0; r < 4; r++) {
            int idx = tid + r * 256;
            int k  = idx >> 5;
            int n4 = (idx & 31) << 2;
            uint4 v = *(const uint4*)(&W[(size_t)(k0 + k) * DD + nBase + n4]);
            *(uint4*)(&Bs[k * BSTRIDE + n4]) = v;
        }
        __syncthreads();

        #pragma unroll
        for (int ks = 0; ks < 4; ks++) {
            int k8 = ks * 8;
            unsigned int af[4][4], bf[4][2];
            #pragma unroll
            for (int mi = 0; mi < 4; mi++) {
                int mr = wm * 64 + mi * 16 + g;
                af[mi][0] = As[(k8 + t) * ASTRIDE + mr];
                af[mi][1] = As[(k8 + t) * ASTRIDE + mr + 8];
                af[mi][2] = As[(k8 + t + 4) * ASTRIDE + mr];
                af[mi][3] = As[(k8 + t + 4) * ASTRIDE + mr + 8];
            }
            #pragma unroll
            for (int ni = 0; ni < 4; ni++) {
                int nc = wn * 32 + ni * 8 + g;
                bf[ni][0] = Bs[(k8 + t) * BSTRIDE + nc];
                bf[ni][1] = Bs[(k8 + t + 4) * BSTRIDE + nc];
            }
            #pragma unroll
            for (int mi = 0; mi < 4; mi++)
                #pragma unroll
                for (int ni = 0; ni < 4; ni++)
                    mma_tf32(acc[mi][ni], af[mi], bf[ni]);
        }
    }

    // epilogue: scale by deg[row], store
    #pragma unroll
    for (int mi = 0; mi < 4; mi++) {
        int r0 = mBase + wm * 64 + mi * 16 + g;
        float d0 = g_deg[r0];
        float d1 = g_deg[r0 + 8];
        #pragma unroll
        for (int ni = 0; ni < 4; ni++) {
            int c = nBase + wn * 32 + ni * 8 + t * 2;
            float2 v0; v0.x = acc[mi][ni][0] * d0; v0.y = acc[mi][ni][1] * d0;
            float2 v1; v1.x = acc[mi][ni][2] * d1; v1.y = acc[mi][ni][3] * d1;
            *(float2*)(&g_bufA[(size_t)r0 * DD + c]) = v0;
            *(float2*)(&g_bufA[(size_t)(r0 + 8) * DD + c]) = v1;
        }
    }
}

// ---------------- SpMM gather: out[i] = relu?(deg[i]*sum_j Z[j] + bias) ----------------
__device__ __forceinline__ void f4acc(float4& a, const float4 b) {
    a.x += b.x; a.y += b.y; a.z += b.z; a.w += b.w;
}

__global__ __launch_bounds__(256)
void spmm_gather(const float* __restrict__ bias, float* __restrict__ outp, int do_relu) {
    int warp = (blockIdx.x * blockDim.x + threadIdx.x) >> 5;
    int lane = threadIdx.x & 31;
    if (warp >= NROWS) return;
    int row = warp;
    int bbase = row & ~(NN - 1);

    const float4* Zv = (const float4*)g_bufA;
    float* out = outp ? outp : g_bufB;

    float4 a0 = make_float4(0.f, 0.f, 0.f, 0.f);
    float4 a1 = a0, a2 = a0, a3 = a0;

    int cnt = g_cnt[row];
    const unsigned short* lst = &g_idx[(size_t)row * MAXD];
    #pragma unroll 2
    for (int k = 0; k < cnt; k++) {
        int j = lst[k];
        const float4* zr = Zv + (size_t)(bbase + j) * (DD / 4);
        float4 v0 = zr[lane];
        float4 v1 = zr[lane + 32];
        float4 v2 = zr[lane + 64];
        float4 v3 = zr[lane + 96];
        f4acc(a0, v0); f4acc(a1, v1); f4acc(a2, v2); f4acc(a3, v3);
    }

    float dv = g_deg[row];
    const float4* bv = (const float4*)bias;
    float4* ov = (float4*)(out + (size_t)row * DD);
    float4 accs[4] = {a0, a1, a2, a3};
    #pragma unroll
    for (int q = 0; q < 4; q++) {
        float4 bq = bv[lane + 32 * q];
        float4 o;
        o.x = accs[q].x * dv + bq.x;
        o.y = accs[q].y * dv + bq.y;
        o.z = accs[q].z * dv + bq.z;
        o.w = accs[q].w * dv + bq.w;
        if (do_relu) {
            o.x = fmaxf(o.x, 0.f); o.y = fmaxf(o.y, 0.f);
            o.z = fmaxf(o.z, 0.f); o.w = fmaxf(o.w, 0.f);
        }
        ov[lane + 32 * q] = o;
    }
}

// ---------------- launch ----------------
extern "C" void kernel_launch(void* const* d_in, const int* in_sizes, int n_in,
                              void* d_out, int out_size) {
    const float* X   = (const float*)d_in[0];
    const float* adj = (const float*)d_in[1];
    const float* W1  = (const float*)d_in[2];
    const float* b1  = (const float*)d_in[3];
    const float* W2  = (const float*)d_in[4];
    const float* b2  = (const float*)d_in[5];
    const float* W3  = (const float*)d_in[6];
    const float* b3  = (const float*)d_in[7];
    float* out = (float*)d_out;

    build_seg<<<dim3(NN / 32, NB), dim3(32, SEGS)>>>(adj);
    compact_deg<<<NROWS / 256, 256>>>();
    cvt_w<<<(DD * DD + 255) / 256, 256>>>(W1, 0);
    cvt_w<<<(DD * DD + 255) / 256, 256>>>(W2, 1);
    cvt_w<<<(DD * DD + 255) / 256, 256>>>(W3, 2);

    dim3 ggrid(DD / BN, NROWS / BM);   // (4, 128)
    int sgrid = NROWS * 32 / 256;      // 2048

    gemm_tf32<<<ggrid, 256>>>(X, 0);
    spmm_gather<<<sgrid, 256>>>(b1, nullptr, 1);
    gemm_tf32<<<ggrid, 256>>>(nullptr, 1);
    spmm_gather<<<sgrid, 256>>>(b2, nullptr, 1);
    gemm_tf32<<<ggrid, 256>>>(nullptr, 2);
    spmm_gather<<<sgrid, 256>>>(b3, out, 0);
}

// round 2
// speedup vs baseline: 1.4247x; 1.4247x over previous
#include <cuda_runtime.h>
#include <cuda_fp16.h>
#include <cstdint>
#include <cstddef>

#define NB    4
#define NN    4096
#define DD    512
#define NROWS (NB*NN)      // 16384
#define MAXD  96
#define SEGS  8
#define SEGCAP 32
#define SEGLEN (NN/SEGS)   // 512

// ---------------- scratch (static __device__, no allocs) ----------------
__device__ __half         g_bufZ[NROWS*DD];            // GEMM output (deg-scaled), gather source
__device__ __half         g_bufH[NROWS*DD];            // SpMM output (activations), GEMM A input
__device__ __half         g_Wh[3*DD*DD];               // weights fp16, TRANSPOSED [n][k]
__device__ unsigned short g_seg_idx[NROWS*SEGS*SEGCAP];
__device__ int            g_seg_cnt[NROWS*SEGS];
__device__ unsigned short g_idx[NROWS*MAXD];
__device__ int            g_cnt[NROWS];
__device__ float          g_deg[NROWS];                // rsqrt(colsum)

// ---------------- adjacency structure build ----------------
__global__ void build_seg(const float* __restrict__ adj) {
    int i = blockIdx.x * 32 + threadIdx.x;
    int s = threadIdx.y;
    int b = blockIdx.y;
    int row = b * NN + i;
    unsigned short* out = &g_seg_idx[(size_t)(row * SEGS + s) * SEGCAP];
    const float* colp = adj + (size_t)b * NN * NN + i;
    int j0 = s * SEGLEN;
    int c = 0;
    #pragma unroll 4
    for (int jj = 0; jj < SEGLEN; jj++) {
        int j = j0 + jj;
        float v = colp[(size_t)j * NN];
        if (v != 0.0f) {
            if (c < SEGCAP) out[c] = (unsigned short)j;
            c++;
        }
    }
    g_seg_cnt[row * SEGS + s] = c;
}

__global__ void compact_deg() {
    int row = blockIdx.x * blockDim.x + threadIdx.x;
    if (row >= NROWS) return;
    unsigned short* dst = &g_idx[(size_t)row * MAXD];
    int total = 0;
    int nout = 0;
    for (int s = 0; s < SEGS; s++) {
        int c = g_seg_cnt[row * SEGS + s];
        int cc = c < SEGCAP ? c : SEGCAP;
        const unsigned short* src = &g_seg_idx[(size_t)(row * SEGS + s) * SEGCAP];
        for (int k = 0; k < cc; k++) {
            if (nout < MAXD) dst[nout++] = src[k];
        }
        total += c;
    }
    g_cnt[row] = nout;
    g_deg[row] = rsqrtf((float)total);
}

// ---------------- weights: fp32 [k][n] -> fp16 transposed [n][k], 3 at once ----------------
__global__ void cvt_w3(const float* __restrict__ w0, const float* __restrict__ w1,
                       const float* __restrict__ w2) {
    const float* w = (blockIdx.y == 0) ? w0 : (blockIdx.y == 1) ? w1 : w2;
    int idx = blockIdx.x * blockDim.x + threadIdx.x;
    if (idx < DD * DD) {
        int k = idx >> 9;         // idx / 512
        int n = idx & 511;
        g_Wh[(size_t)blockIdx.y * DD * DD + (size_t)n * DD + k] = __float2half_rn(w[idx]);
    }
}

// ---------------- fp16 tensor-core GEMM, fp32 accumulate ----------------
// C[m,n] = sum_k A[m,k]*W[k,n]; writes g_bufZ[m,n] = (half)(deg[m]*C[m,n])
// BM=128, BN=128, BK=32; 256 threads (8 warps), warp tile 64x32, mma m16n8k16.
#define BM 128
#define BN 128
#define BK 32
#define SST 40   // smem row stride in halfs (32 + 8 pad)

__device__ __forceinline__ float2 h2f2(unsigned int u) {
    __half2 h = *reinterpret_cast<__half2*>(&u);
    return __half22float2(h);
}

__device__ __forceinline__ void mma_f16(float* c, const unsigned int* a, const unsigned int* b) {
    asm volatile(
        "mma.sync.aligned.m16n8k16.row.col.f32.f16.f16.f32 "
        "{%0,%1,%2,%3}, {%4,%5,%6,%7}, {%8,%9}, {%0,%1,%2,%3};"
        : "+f"(c[0]), "+f"(c[1]), "+f"(c[2]), "+f"(c[3])
        : "r"(a[0]), "r"(a[1]), "r"(a[2]), "r"(a[3]), "r"(b[0]), "r"(b[1]));
}

template <bool F32IN>
__global__ __launch_bounds__(256)
void gemm_f16(const float* __restrict__ Xf, int which) {
    const __half* Ah = g_bufH;
    const __half* Wh = &g_Wh[(size_t)which * DD * DD];

    __shared__ __half As[BM * SST];   // [m][k]
    __shared__ __half Bs[BN * SST];   // [n][k]

    const int tid  = threadIdx.x;
    const int lane = tid & 31;
    const int wid  = tid >> 5;
    const int wm   = wid & 1;
    const int wn   = wid >> 1;
    const int g    = lane >> 2;
    const int t    = lane & 3;

    const int nBase = blockIdx.x * BN;
    const int mBase = blockIdx.y * BM;

    float acc[4][4][4];
    #pragma unroll
    for (int mi = 0; mi < 4; mi++)
        #pragma unroll
        for (int ni = 0; ni < 4; ni++)
            #pragma unroll
            for (int q = 0; q < 4; q++) acc[mi][ni][q] = 0.0f;

    // prefetch registers
    float4 aldf[4];
    uint4  aldh[2];
    uint4  bld[2];

    // --- load tile k0 into regs ---
    auto loadA = [&](int k0) {
        if (F32IN) {
            #pragma unroll
            for (int r = 0; r < 4; r++) {
                int idx = tid + r * 256;
                int m  = idx >> 3;
                int kq = (idx & 7) << 2;
                aldf[r] = *(const float4*)(Xf + (size_t)(mBase + m) * DD + k0 + kq);
            }
        } else {
            #pragma unroll
            for (int r = 0; r < 2; r++) {
                int idx = tid + r * 256;
                int m  = idx >> 2;
                int kq = (idx & 3) << 3;
                aldh[r] = *(const uint4*)(Ah + (size_t)(mBase + m) * DD + k0 + kq);
            }
        }
    };
    auto loadB = [&](int k0) {
        #pragma unroll
        for (int r = 0; r < 2; r++) {
            int idx = tid + r * 256;
            int n  = idx >> 2;
            int kq = (idx & 3) << 3;
            bld[r] = *(const uint4*)(Wh + (size_t)(nBase + n) * DD + k0 + kq);
        }
    };
    auto storeA = [&]() {
        if (F32IN) {
            #pragma unroll
            for (int r = 0; r < 4; r++) {
                int idx = tid + r * 256;
                int m  = idx >> 3;
                int kq = (idx & 7) << 2;
                __half2 lo = __floats2half2_rn(aldf[r].x, aldf[r].y);
                __half2 hi = __floats2half2_rn(aldf[r].z, aldf[r].w);
                *(__half2*)(&As[m * SST + kq])     = lo;
                *(__half2*)(&As[m * SST + kq + 2]) = hi;
            }
        } else {
            #pragma unroll
            for (int r = 0; r < 2; r++) {
                int idx = tid + r * 256;
                int m  = idx >> 2;
                int kq = (idx & 3) << 3;
                *(uint4*)(&As[m * SST + kq]) = aldh[r];
            }
        }
    };
    auto storeB = [&]() {
        #pragma unroll
        for (int r = 0; r < 2; r++) {
            int idx = tid + r * 256;
            int n  = idx >> 2;
            int kq = (idx & 3) << 3;
            *(uint4*)(&Bs[n * SST + kq]) = bld[r];
        }
    };

    const unsigned int* As2 = (const unsigned int*)As;   // half2 view, stride SST/2=20
    const unsigned int* Bs2 = (const unsigned int*)Bs;

    loadA(0); loadB(0);

    for (int kt = 0; kt < DD / BK; kt++) {
        storeA(); storeB();
        __syncthreads();
        if (kt < DD / BK - 1) { loadA((kt + 1) * BK); loadB((kt + 1) * BK); }

        #pragma unroll
        for (int ks = 0; ks < 2; ks++) {
            int koff = ks * 8;   // in half2 units (16 halfs)
            unsigned int af[4][4], bf[4][2];
            #pragma unroll
            for (int mi = 0; mi < 4; mi++) {
                int mr = wm * 64 + mi * 16 + g;
                af[mi][0] = As2[mr * 20 + t + koff];
                af[mi][1] = As2[(mr + 8) * 20 + t + koff];
                af[mi][2] = As2[mr * 20 + t + 4 + koff];
                af[mi][3] = As2[(mr + 8) * 20 + t + 4 + koff];
            }
            #pragma unroll
            for (int ni = 0; ni < 4; ni++) {
                int nc = wn * 32 + ni * 8 + g;
                bf[ni][0] = Bs2[nc * 20 + t + koff];
                bf[ni][1] = Bs2[nc * 20 + t + 4 + koff];
            }
            #pragma unroll
            for (int mi = 0; mi < 4; mi++)
                #pragma unroll
                for (int ni = 0; ni < 4; ni++)
                    mma_f16(acc[mi][ni], af[mi], bf[ni]);
        }
        __syncthreads();
    }

    // epilogue: scale by deg[row], store fp16
    #pragma unroll
    for (int mi = 0; mi < 4; mi++) {
        int r0 = mBase + wm * 64 + mi * 16 + g;
        float d0 = g_deg[r0];
        float d1 = g_deg[r0 + 8];
        #pragma unroll
        for (int ni = 0; ni < 4; ni++) {
            int c = nBase + wn * 32 + ni * 8 + t * 2;
            __half2 v0 = __floats2half2_rn(acc[mi][ni][0] * d0, acc[mi][ni][1] * d0);
            __half2 v1 = __floats2half2_rn(acc[mi][ni][2] * d1, acc[mi][ni][3] * d1);
            *(__half2*)(&g_bufZ[(size_t)r0 * DD + c])       = v0;
            *(__half2*)(&g_bufZ[(size_t)(r0 + 8) * DD + c]) = v1;
        }
    }
}

// ---------------- SpMM gather (fp16 rows, fp32 accumulate) ----------------
// out[i] = act(deg[i] * sum_{j in N(i)} Z[j] + bias)
__device__ __forceinline__ void acc8(float* a, uint4 q) {
    float2 f;
    f = h2f2(q.x); a[0] += f.x; a[1] += f.y;
    f = h2f2(q.y); a[2] += f.x; a[3] += f.y;
    f = h2f2(q.z); a[4] += f.x; a[5] += f.y;
    f = h2f2(q.w); a[6] += f.x; a[7] += f.y;
}

__global__ __launch_bounds__(256)
void spmm_gather(const float* __restrict__ bias, float* __restrict__ outp, int do_relu) {
    int warp = (blockIdx.x * blockDim.x + threadIdx.x) >> 5;
    int lane = threadIdx.x & 31;
    if (warp >= NROWS) return;
    int row = warp;
    int bbase = row & ~(NN - 1);

    const uint4* Z4 = (const uint4*)g_bufZ;   // 64 uint4 per row

    float acc[16];
    #pragma unroll
    for (int q = 0; q < 16; q++) acc[q] = 0.0f;

    int cnt = g_cnt[row];
    const unsigned short* lst = &g_idx[(size_t)row * MAXD];
    #pragma unroll 2
    for (int k = 0; k < cnt; k++) {
        int j = lst[k];
        const uint4* zr = Z4 + (size_t)(bbase + j) * (DD / 8);
        uint4 q0 = zr[lane];
        uint4 q1 = zr[lane + 32];
        acc8(acc, q0);
        acc8(acc + 8, q1);
    }

    float dv = g_deg[row];
    const float4* bv = (const float4*)bias;
    // lane covers columns [8*lane, 8*lane+8) and [256+8*lane, 256+8*lane+8)
    float o[16];
    #pragma unroll
    for (int h = 0; h < 2; h++) {
        float4 ba = bv[h * 64 + 2 * lane];
        float4 bb = bv[h * 64 + 2 * lane + 1];
        float* a = acc + h * 8;
        float* oo = o + h * 8;
        oo[0] = a[0] * dv + ba.x; oo[1] = a[1] * dv + ba.y;
        oo[2] = a[2] * dv + ba.z; oo[3] = a[3] * dv + ba.w;
        oo[4] = a[4] * dv + bb.x; oo[5] = a[5] * dv + bb.y;
        oo[6] = a[6] * dv + bb.z; oo[7] = a[7] * dv + bb.w;
    }
    if (do_relu) {
        #pragma unroll
        for (int q = 0; q < 16; q++) o[q] = fmaxf(o[q], 0.0f);
    }

    if (outp) {
        // final layer: fp32 out
        float4* ov = (float4*)(outp + (size_t)row * DD);
        #pragma unroll
        for (int h = 0; h < 2; h++) {
            ov[h * 64 + 2 * lane]     = make_float4(o[h*8+0], o[h*8+1], o[h*8+2], o[h*8+3]);
            ov[h * 64 + 2 * lane + 1] = make_float4(o[h*8+4], o[h*8+5], o[h*8+6], o[h*8+7]);
        }
    } else {
        // hidden layer: fp16 out
        uint4* hv = (uint4*)(g_bufH + (size_t)row * DD);
        #pragma unroll
        for (int h = 0; h < 2; h++) {
            uint4 u;
            __half2 p0 = __floats2half2_rn(o[h*8+0], o[h*8+1]);
            __half2 p1 = __floats2half2_rn(o[h*8+2], o[h*8+3]);
            __half2 p2 = __floats2half2_rn(o[h*8+4], o[h*8+5]);
            __half2 p3 = __floats2half2_rn(o[h*8+6], o[h*8+7]);
            u.x = *(unsigned int*)&p0; u.y = *(unsigned int*)&p1;
            u.z = *(unsigned int*)&p2; u.w = *(unsigned int*)&p3;
            hv[h * 32 + lane] = u;
        }
    }
}

// ---------------- launch ----------------
extern "C" void kernel_launch(void* const* d_in, const int* in_sizes, int n_in,
                              void* d_out, int out_size) {
    const float* X   = (const float*)d_in[0];
    const float* adj = (const float*)d_in[1];
    const float* W1  = (const float*)d_in[2];
    const float* b1  = (const float*)d_in[3];
    const float* W2  = (const float*)d_in[4];
    const float* b2  = (const float*)d_in[5];
    const float* W3  = (const float*)d_in[6];
    const float* b3  = (const float*)d_in[7];
    float* out = (float*)d_out;

    build_seg<<<dim3(NN / 32, NB), dim3(32, SEGS)>>>(adj);
    compact_deg<<<NROWS / 256, 256>>>();
    cvt_w3<<<dim3((DD * DD + 255) / 256, 3), 256>>>(W1, W2, W3);

    dim3 ggrid(DD / BN, NROWS / BM);   // (4, 128)
    int sgrid = NROWS * 32 / 256;      // 2048

    gemm_f16<true><<<ggrid, 256>>>(X, 0);
    spmm_gather<<<sgrid, 256>>>(b1, nullptr, 1);
    gemm_f16<false><<<ggrid, 256>>>(nullptr, 1);
    spmm_gather<<<sgrid, 256>>>(b2, nullptr, 1);
    gemm_f16<false><<<ggrid, 256>>>(nullptr, 2);
    spmm_gather<<<sgrid, 256>>>(b3, out, 0);
}

// round 4
// speedup vs baseline: 1.4437x; 1.0134x over previous
#include <cuda_runtime.h>
#include <cuda_fp16.h>
#include <cstdint>
#include <cstddef>

#define NB    4
#define NN    4096
#define DD    512
#define NROWS (NB*NN)      // 16384
#define MAXD  96
#define SEGS  8
#define SEGCAP 32
#define SEGLEN (NN/SEGS)   // 512

// ---------------- scratch (static __device__, no allocs) ----------------
__device__ __half         g_bufZ[NROWS*DD];            // GEMM output (UNscaled XW), gather source
__device__ __half         g_bufH[NROWS*DD];            // activations / fp16 X, GEMM A input
__device__ __half         g_Wh[3*DD*DD];               // weights fp16, TRANSPOSED [n][k]
__device__ unsigned short g_seg_idx[NROWS*SEGS*SEGCAP];
__device__ int            g_seg_cnt[NROWS*SEGS];
__device__ unsigned short g_idx[NROWS*MAXD];
__device__ int            g_cnt[NROWS];
__device__ float          g_deg[NROWS];                // rsqrt(colsum)

// ---------------- adjacency structure build ----------------
__global__ void build_seg(const float* __restrict__ adj) {
    int i = blockIdx.x * 32 + threadIdx.x;
    int s = threadIdx.y;
    int b = blockIdx.y;
    int row = b * NN + i;
    unsigned short* out = &g_seg_idx[(size_t)(row * SEGS + s) * SEGCAP];
    const float* colp = adj + (size_t)b * NN * NN + i;
    int j0 = s * SEGLEN;
    int c = 0;
    #pragma unroll 4
    for (int jj = 0; jj < SEGLEN; jj++) {
        int j = j0 + jj;
        float v = colp[(size_t)j * NN];
        if (v != 0.0f) {
            if (c < SEGCAP) out[c] = (unsigned short)j;
            c++;
        }
    }
    g_seg_cnt[row * SEGS + s] = c;
}

__global__ void compact_deg() {
    int row = blockIdx.x * blockDim.x + threadIdx.x;
    if (row >= NROWS) return;
    unsigned short* dst = &g_idx[(size_t)row * MAXD];
    int total = 0;
    int nout = 0;
    for (int s = 0; s < SEGS; s++) {
        int c = g_seg_cnt[row * SEGS + s];
        int cc = c < SEGCAP ? c : SEGCAP;
        const unsigned short* src = &g_seg_idx[(size_t)(row * SEGS + s) * SEGCAP];
        for (int k = 0; k < cc; k++) {
            if (nout < MAXD) dst[nout++] = src[k];
        }
        total += c;
    }
    g_cnt[row] = nout;
    g_deg[row] = rsqrtf((float)total);
}

// ---------------- weights: fp32 [k][n] -> fp16 transposed [n][k] ----------------
__global__ void cvt_w3(const float* __restrict__ w0, const float* __restrict__ w1,
                       const float* __restrict__ w2) {
    const float* w = (blockIdx.y == 0) ? w0 : (blockIdx.y == 1) ? w1 : w2;
    int idx = blockIdx.x * blockDim.x + threadIdx.x;
    if (idx < DD * DD) {
        int k = idx >> 9;
        int n = idx & 511;
        g_Wh[(size_t)blockIdx.y * DD * DD + (size_t)n * DD + k] = __float2half_rn(w[idx]);
    }
}

// ---------------- X fp32 -> fp16 into g_bufH ----------------
__global__ void cvt_x(const float* __restrict__ X) {
    int i = blockIdx.x * blockDim.x + threadIdx.x;   // over NROWS*DD/4
    float4 v = ((const float4*)X)[i];
    __half2 a = __floats2half2_rn(v.x, v.y);
    __half2 b = __floats2half2_rn(v.z, v.w);
    uint2 u;
    u.x = *(unsigned int*)&a;
    u.y = *(unsigned int*)&b;
    ((uint2*)g_bufH)[i] = u;
}

// ---------------- fp16 tensor-core GEMM, cp.async 3-stage + ldmatrix ----------------
// C[m,n] = sum_k A[m,k]*W[k,n]; writes g_bufZ[m,n] = (half)C[m,n]  (no deg scale)
#define BM 128
#define BN 128
#define BK 32
#define NT (DD/BK)          // 16 k-tiles
#define SST 40              // smem row stride in halfs (32 + 8 pad)
#define STAGE_HALFS (BM*SST)          // 5120 halfs = 10240 B per stage (A or B)
#define STAGE_BYTES (STAGE_HALFS*2)
#define B_REGION (3*STAGE_BYTES)      // Bs starts after 3 A stages
#define GEMM_SMEM (6*STAGE_BYTES)     // 61440 B

__device__ __forceinline__ void cp16(unsigned int saddr, const void* g) {
    asm volatile("cp.async.cg.shared.global [%0], [%1], 16;\n" :: "r"(saddr), "l"(g));
}
__device__ __forceinline__ void ldsm4(unsigned int* r, unsigned int saddr) {
    asm volatile("ldmatrix.sync.aligned.m8n8.x4.shared.b16 {%0,%1,%2,%3}, [%4];"
                 : "=r"(r[0]), "=r"(r[1]), "=r"(r[2]), "=r"(r[3]) : "r"(saddr));
}
__device__ __forceinline__ void mma_f16(float* c, const unsigned int* a,
                                        unsigned int b0, unsigned int b1) {
    asm volatile(
        "mma.sync.aligned.m16n8k16.row.col.f32.f16.f16.f32 "
        "{%0,%1,%2,%3}, {%4,%5,%6,%7}, {%8,%9}, {%0,%1,%2,%3};"
        : "+f"(c[0]), "+f"(c[1]), "+f"(c[2]), "+f"(c[3])
        : "r"(a[0]), "r"(a[1]), "r"(a[2]), "r"(a[3]), "r"(b0), "r"(b1));
}

__global__ __launch_bounds__(256, 2)
void gemm_f16(int which) {
    extern __shared__ __align__(16) char sm[];
    const __half* Ah = g_bufH;
    const __half* Wh = &g_Wh[(size_t)which * DD * DD];

    const int tid  = threadIdx.x;
    const int lane = tid & 31;
    const int wid  = tid >> 5;
    const int wm   = wid & 1;
    const int wn   = wid >> 1;

    const int nBase = blockIdx.x * BN;
    const int mBase = blockIdx.y * BM;

    unsigned int smemBase = (unsigned int)__cvta_generic_to_shared(sm);

    // cp.async staging: thread writes one 16B chunk, twice per tile per operand
    const int cm = tid >> 2;             // row (m or n), 0..63 (+64 second iter)
    const int ck = (tid & 3) << 3;       // k offset in halfs (0,8,16,24)

    // ldmatrix per-lane addresses (byte offsets within a stage)
    const unsigned int aLdOff = (((unsigned int)(wm * 64 + (lane & 15)) * SST + ((lane >> 4) * 8)) * 2);
    const unsigned int bLdOff = (((unsigned int)(wn * 32 + (lane & 7)) * SST + ((lane >> 3) * 8)) * 2);

    float acc[4][4][4];
    #pragma unroll
    for (int mi = 0; mi < 4; mi++)
        #pragma unroll
        for (int ni = 0; ni < 4; ni++)
            #pragma unroll
            for (int q = 0; q < 4; q++) acc[mi][ni][q] = 0.0f;

    auto issue = [&](int kt, int st) {
        int k0 = kt * BK;
        unsigned int aBase = smemBase + st * STAGE_BYTES;
        unsigned int bBase = smemBase + B_REGION + st * STAGE_BYTES;
        #pragma unroll
        for (int r = 0; r < 2; r++) {
            int m = cm + r * 64;
            cp16(aBase + (m * SST + ck) * 2, Ah + (size_t)(mBase + m) * DD + k0 + ck);
            cp16(bBase + (m * SST + ck) * 2, Wh + (size_t)(nBase + m) * DD + k0 + ck);
        }
        asm volatile("cp.async.commit_group;\n");
    };

    issue(0, 0);
    issue(1, 1);

    for (int kt = 0; kt < NT; kt++) {
        int st = kt % 3;
        if (kt == NT - 1) asm volatile("cp.async.wait_group 0;\n");
        else              asm volatile("cp.async.wait_group 1;\n");
        __syncthreads();
        if (kt + 2 < NT) issue(kt + 2, (kt + 2) % 3);

        unsigned int aS = smemBase + st * STAGE_BYTES + aLdOff;
        unsigned int bS = smemBase + B_REGION + st * STAGE_BYTES + bLdOff;

        unsigned int bq[4][4];
        #pragma unroll
        for (int ni = 0; ni < 4; ni++)
            ldsm4(bq[ni], bS + ni * (8 * SST * 2));   // B is [n][k]: NON-trans gives b-fragment

        #pragma unroll
        for (int ks = 0; ks < 2; ks++) {
            unsigned int af[4][4];
            #pragma unroll
            for (int mi = 0; mi < 4; mi++)
                ldsm4(af[mi], aS + mi * (16 * SST * 2) + ks * 32);
            #pragma unroll
            for (int mi = 0; mi < 4; mi++)
                #pragma unroll
                for (int ni = 0; ni < 4; ni++)
                    mma_f16(acc[mi][ni], af[mi], bq[ni][2 * ks], bq[ni][2 * ks + 1]);
        }
    }

    // epilogue: store fp16 (unscaled)
    const int g = lane >> 2;
    const int t = lane & 3;
    #pragma unroll
    for (int mi = 0; mi < 4; mi++) {
        int r0 = mBase + wm * 64 + mi * 16 + g;
        #pragma unroll
        for (int ni = 0; ni < 4; ni++) {
            int c = nBase + wn * 32 + ni * 8 + t * 2;
            __half2 v0 = __floats2half2_rn(acc[mi][ni][0], acc[mi][ni][1]);
            __half2 v1 = __floats2half2_rn(acc[mi][ni][2], acc[mi][ni][3]);
            *(__half2*)(&g_bufZ[(size_t)r0 * DD + c])       = v0;
            *(__half2*)(&g_bufZ[(size_t)(r0 + 8) * DD + c]) = v1;
        }
    }
}

// ---------------- SpMM gather (fp16 rows, fp32 accumulate, deg_j applied here) ----------------
__device__ __forceinline__ float2 h2f2(unsigned int u) {
    __half2 h = *reinterpret_cast<__half2*>(&u);
    return __half22float2(h);
}
__device__ __forceinline__ void acc8(float* a, uint4 q, float dj) {
    float2 f;
    f = h2f2(q.x); a[0] += dj * f.x; a[1] += dj * f.y;
    f = h2f2(q.y); a[2] += dj * f.x; a[3] += dj * f.y;
    f = h2f2(q.z); a[4] += dj * f.x; a[5] += dj * f.y;
    f = h2f2(q.w); a[6] += dj * f.x; a[7] += dj * f.y;
}

__global__ __launch_bounds__(256)
void spmm_gather(const float* __restrict__ bias, float* __restrict__ outp, int do_relu) {
    int warp = (blockIdx.x * blockDim.x + threadIdx.x) >> 5;
    int lane = threadIdx.x & 31;
    if (warp >= NROWS) return;
    int row = warp;
    int bbase = row & ~(NN - 1);

    const uint4* Z4 = (const uint4*)g_bufZ;

    float acc[16];
    #pragma unroll
    for (int q = 0; q < 16; q++) acc[q] = 0.0f;

    int cnt = g_cnt[row];
    const unsigned short* lst = &g_idx[(size_t)row * MAXD];
    #pragma unroll 2
    for (int k = 0; k < cnt; k++) {
        int j = lst[k];
        float dj = g_deg[bbase + j];
        const uint4* zr = Z4 + (size_t)(bbase + j) * (DD / 8);
        uint4 q0 = zr[lane];
        uint4 q1 = zr[lane + 32];
        acc8(acc, q0, dj);
        acc8(acc + 8, q1, dj);
    }

    float dv = g_deg[row];
    const float4* bv = (const float4*)bias;
    float o[16];
    #pragma unroll
    for (int h = 0; h < 2; h++) {
        float4 ba = bv[h * 64 + 2 * lane];
        float4 bb = bv[h * 64 + 2 * lane + 1];
        float* a = acc + h * 8;
        float* oo = o + h * 8;
        oo[0] = a[0] * dv + ba.x; oo[1] = a[1] * dv + ba.y;
        oo[2] = a[2] * dv + ba.z; oo[3] = a[3] * dv + ba.w;
        oo[4] = a[4] * dv + bb.x; oo[5] = a[5] * dv + bb.y;
        oo[6] = a[6] * dv + bb.z; oo[7] = a[7] * dv + bb.w;
    }
    if (do_relu) {
        #pragma unroll
        for (int q = 0; q < 16; q++) o[q] = fmaxf(o[q], 0.0f);
    }

    if (outp) {
        float4* ov = (float4*)(outp + (size_t)row * DD);
        #pragma unroll
        for (int h = 0; h < 2; h++) {
            ov[h * 64 + 2 * lane]     = make_float4(o[h*8+0], o[h*8+1], o[h*8+2], o[h*8+3]);
            ov[h * 64 + 2 * lane + 1] = make_float4(o[h*8+4], o[h*8+5], o[h*8+6], o[h*8+7]);
        }
    } else {
        uint4* hv = (uint4*)(g_bufH + (size_t)row * DD);
        #pragma unroll
        for (int h = 0; h < 2; h++) {
            uint4 u;
            __half2 p0 = __floats2half2_rn(o[h*8+0], o[h*8+1]);
            __half2 p1 = __floats2half2_rn(o[h*8+2], o[h*8+3]);
            __half2 p2 = __floats2half2_rn(o[h*8+4], o[h*8+5]);
            __half2 p3 = __floats2half2_rn(o[h*8+6], o[h*8+7]);
            u.x = *(unsigned int*)&p0; u.y = *(unsigned int*)&p1;
            u.z = *(unsigned int*)&p2; u.w = *(unsigned int*)&p3;
            hv[h * 32 + lane] = u;
        }
    }
}

// ---------------- launch ----------------
extern "C" void kernel_launch(void* const* d_in, const int* in_sizes, int n_in,
                              void* d_out, int out_size) {
    const float* X   = (const float*)d_in[0];
    const float* adj = (const float*)d_in[1];
    const float* W1  = (const float*)d_in[2];
    const float* b1  = (const float*)d_in[3];
    const float* W2  = (const float*)d_in[4];
    const float* b2  = (const float*)d_in[5];
    const float* W3  = (const float*)d_in[6];
    const float* b3  = (const float*)d_in[7];
    float* out = (float*)d_out;

    static cudaStream_t s2 = nullptr;
    static cudaEvent_t evFork = nullptr, evJoin = nullptr;
    static bool smemSet = false;
    if (!s2) {
        cudaStreamCreateWithFlags(&s2, cudaStreamNonBlocking);
        cudaEventCreateWithFlags(&evFork, cudaEventDisableTiming);
        cudaEventCreateWithFlags(&evJoin, cudaEventDisableTiming);
    }
    if (!smemSet) {
        cudaFuncSetAttribute(gemm_f16, cudaFuncAttributeMaxDynamicSharedMemorySize, GEMM_SMEM);
        smemSet = true;
    }

    dim3 ggrid(DD / BN, NROWS / BM);   // (4, 128)
    int sgrid = NROWS * 32 / 256;      // 2048

    // fork: adjacency build on s2 overlaps cvt + layer-1 GEMM on main stream
    cudaEventRecord(evFork, 0);
    cudaStreamWaitEvent(s2, evFork, 0);
    build_seg<<<dim3(NN / 32, NB), dim3(32, SEGS), 0, s2>>>(adj);
    compact_deg<<<NROWS / 256, 256, 0, s2>>>();
    cudaEventRecord(evJoin, s2);

    cvt_w3<<<dim3((DD * DD + 255) / 256, 3), 256>>>(W1, W2, W3);
    cvt_x<<<(NROWS * DD / 4 + 255) / 256, 256>>>(X);
    gemm_f16<<<ggrid, 256, GEMM_SMEM>>>(0);

    cudaStreamWaitEvent(0, evJoin, 0);

    spmm_gather<<<sgrid, 256>>>(b1, nullptr, 1);
    gemm_f16<<<ggrid, 256, GEMM_SMEM>>>(1);
    spmm_gather<<<sgrid, 256>>>(b2, nullptr, 1);
    gemm_f16<<<ggrid, 256, GEMM_SMEM>>>(2);
    spmm_gather<<<sgrid, 256>>>(b3, out, 0);
}

// round 7
// speedup vs baseline: 1.5837x; 1.0970x over previous
#include <cuda_runtime.h>
#include <cuda_fp16.h>
#include <cstdint>
#include <cstddef>

#define NB    4
#define NN    4096
#define DD    512
#define NROWS (NB*NN)      // 16384
#define HROWS (NROWS/2)    // 8192 per batch-pair
#define MAXD  96
#define SEGS  8
#define SEGCAP 32
#define SEGLEN (NN/SEGS)   // 512

// ---------------- scratch (static __device__, no allocs) ----------------
__device__ __half         g_bufZ[NROWS*DD];            // GEMM output (UNscaled XW), gather source
__device__ __half         g_bufH[NROWS*DD];            // activations / fp16 X, GEMM A input
__device__ __half         g_Wh[3*DD*DD];               // weights fp16, TRANSPOSED [n][k]
__device__ unsigned short g_seg_idx[NROWS*SEGS*SEGCAP];
__device__ int            g_seg_cnt[NROWS*SEGS];
__device__ unsigned short g_idx[NROWS*MAXD];
__device__ int            g_cnt[NROWS];
__device__ float          g_deg[NROWS];                // rsqrt(colsum)

// ---------------- adjacency structure build ----------------
__global__ void build_seg(const float* __restrict__ adj) {
    int i = blockIdx.x * 32 + threadIdx.x;
    int s = threadIdx.y;
    int b = blockIdx.y;
    int row = b * NN + i;
    unsigned short* out = &g_seg_idx[(size_t)(row * SEGS + s) * SEGCAP];
    const float* colp = adj + (size_t)b * NN * NN + i;
    int j0 = s * SEGLEN;
    int c = 0;
    #pragma unroll 4
    for (int jj = 0; jj < SEGLEN; jj++) {
        int j = j0 + jj;
        float v = colp[(size_t)j * NN];
        if (v != 0.0f) {
            if (c < SEGCAP) out[c] = (unsigned short)j;
            c++;
        }
    }
    g_seg_cnt[row * SEGS + s] = c;
}

__global__ void compact_deg() {
    int row = blockIdx.x * blockDim.x + threadIdx.x;
    if (row >= NROWS) return;
    unsigned short* dst = &g_idx[(size_t)row * MAXD];
    int total = 0;
    int nout = 0;
    for (int s = 0; s < SEGS; s++) {
        int c = g_seg_cnt[row * SEGS + s];
        int cc = c < SEGCAP ? c : SEGCAP;
        const unsigned short* src = &g_seg_idx[(size_t)(row * SEGS + s) * SEGCAP];
        for (int k = 0; k < cc; k++) {
            if (nout < MAXD) dst[nout++] = src[k];
        }
        total += c;
    }
    g_cnt[row] = nout;
    g_deg[row] = rsqrtf((float)total);
}

// ---------------- weights: fp32 [k][n] -> fp16 transposed [n][k] ----------------
__global__ void cvt_w3(const float* __restrict__ w0, const float* __restrict__ w1,
                       const float* __restrict__ w2) {
    const float* w = (blockIdx.y == 0) ? w0 : (blockIdx.y == 1) ? w1 : w2;
    int idx = blockIdx.x * blockDim.x + threadIdx.x;
    if (idx < DD * DD) {
        int k = idx >> 9;
        int n = idx & 511;
        g_Wh[(size_t)blockIdx.y * DD * DD + (size_t)n * DD + k] = __float2half_rn(w[idx]);
    }
}

// ---------------- X fp32 -> fp16 into g_bufH ----------------
__global__ void cvt_x(const float* __restrict__ X) {
    int i = blockIdx.x * blockDim.x + threadIdx.x;
    float4 v = ((const float4*)X)[i];
    __half2 a = __floats2half2_rn(v.x, v.y);
    __half2 b = __floats2half2_rn(v.z, v.w);
    uint2 u;
    u.x = *(unsigned int*)&a;
    u.y = *(unsigned int*)&b;
    ((uint2*)g_bufH)[i] = u;
}

// ---------------- fp16 tensor-core GEMM, cp.async 3-stage + ldmatrix ----------------
// C[m,n] = sum_k A[m,k]*W[k,n]; writes g_bufZ[m,n] = (half)C[m,n]  (no deg scale)
#define BM 128
#define BN 128
#define BK 32
#define NT (DD/BK)          // 16 k-tiles
#define SST 40              // smem row stride in halfs (32 + 8 pad)
#define STAGE_HALFS (BM*SST)
#define STAGE_BYTES (STAGE_HALFS*2)
#define B_REGION (3*STAGE_BYTES)
#define GEMM_SMEM (6*STAGE_BYTES)     // 61440 B

__device__ __forceinline__ void cp16(unsigned int saddr, const void* g) {
    asm volatile("cp.async.cg.shared.global [%0], [%1], 16;\n" :: "r"(saddr), "l"(g));
}
__device__ __forceinline__ void ldsm4(unsigned int* r, unsigned int saddr) {
    asm volatile("ldmatrix.sync.aligned.m8n8.x4.shared.b16 {%0,%1,%2,%3}, [%4];"
                 : "=r"(r[0]), "=r"(r[1]), "=r"(r[2]), "=r"(r[3]) : "r"(saddr));
}
__device__ __forceinline__ void mma_f16(float* c, const unsigned int* a,
                                        unsigned int b0, unsigned int b1) {
    asm volatile(
        "mma.sync.aligned.m16n8k16.row.col.f32.f16.f16.f32 "
        "{%0,%1,%2,%3}, {%4,%5,%6,%7}, {%8,%9}, {%0,%1,%2,%3};"
        : "+f"(c[0]), "+f"(c[1]), "+f"(c[2]), "+f"(c[3])
        : "r"(a[0]), "r"(a[1]), "r"(a[2]), "r"(a[3]), "r"(b0), "r"(b1));
}

__global__ __launch_bounds__(256, 2)
void gemm_f16(int which, int rowOff) {
    extern __shared__ __align__(16) char sm[];
    const __half* Ah = g_bufH;
    const __half* Wh = &g_Wh[(size_t)which * DD * DD];

    const int tid  = threadIdx.x;
    const int lane = tid & 31;
    const int wid  = tid >> 5;
    const int wm   = wid & 1;
    const int wn   = wid >> 1;

    const int nBase = blockIdx.x * BN;
    const int mBase = rowOff + blockIdx.y * BM;

    unsigned int smemBase = (unsigned int)__cvta_generic_to_shared(sm);

    const int cm = tid >> 2;
    const int ck = (tid & 3) << 3;

    const unsigned int aLdOff = (((unsigned int)(wm * 64 + (lane & 15)) * SST + ((lane >> 4) * 8)) * 2);
    const unsigned int bLdOff = (((unsigned int)(wn * 32 + (lane & 7)) * SST + ((lane >> 3) * 8)) * 2);

    float acc[4][4][4];
    #pragma unroll
    for (int mi = 0; mi < 4; mi++)
        #pragma unroll
        for (int ni = 0; ni < 4; ni++)
            #pragma unroll
            for (int q = 0; q < 4; q++) acc[mi][ni][q] = 0.0f;

    auto issue = [&](int kt, int st) {
        int k0 = kt * BK;
        unsigned int aBase = smemBase + st * STAGE_BYTES;
        unsigned int bBase = smemBase + B_REGION + st * STAGE_BYTES;
        #pragma unroll
        for (int r = 0; r < 2; r++) {
            int m = cm + r * 64;
            cp16(aBase + (m * SST + ck) * 2, Ah + (size_t)(mBase + m) * DD + k0 + ck);
            cp16(bBase + (m * SST + ck) * 2, Wh + (size_t)(nBase + m) * DD + k0 + ck);
        }
        asm volatile("cp.async.commit_group;\n");
    };

    issue(0, 0);
    issue(1, 1);

    for (int kt = 0; kt < NT; kt++) {
        int st = kt % 3;
        if (kt == NT - 1) asm volatile("cp.async.wait_group 0;\n");
        else              asm volatile("cp.async.wait_group 1;\n");
        __syncthreads();
        if (kt + 2 < NT) issue(kt + 2, (kt + 2) % 3);

        unsigned int aS = smemBase + st * STAGE_BYTES + aLdOff;
        unsigned int bS = smemBase + B_REGION + st * STAGE_BYTES + bLdOff;

        unsigned int bq[4][4];
        #pragma unroll
        for (int ni = 0; ni < 4; ni++)
            ldsm4(bq[ni], bS + ni * (8 * SST * 2));   // B is [n][k]: NON-trans

        #pragma unroll
        for (int ks = 0; ks < 2; ks++) {
            unsigned int af[4][4];
            #pragma unroll
            for (int mi = 0; mi < 4; mi++)
                ldsm4(af[mi], aS + mi * (16 * SST * 2) + ks * 32);
            #pragma unroll
            for (int mi = 0; mi < 4; mi++)
                #pragma unroll
                for (int ni = 0; ni < 4; ni++)
                    mma_f16(acc[mi][ni], af[mi], bq[ni][2 * ks], bq[ni][2 * ks + 1]);
        }
    }

    const int g = lane >> 2;
    const int t = lane & 3;
    #pragma unroll
    for (int mi = 0; mi < 4; mi++) {
        int r0 = mBase + wm * 64 + mi * 16 + g;
        #pragma unroll
        for (int ni = 0; ni < 4; ni++) {
            int c = nBase + wn * 32 + ni * 8 + t * 2;
            __half2 v0 = __floats2half2_rn(acc[mi][ni][0], acc[mi][ni][1]);
            __half2 v1 = __floats2half2_rn(acc[mi][ni][2], acc[mi][ni][3]);
            *(__half2*)(&g_bufZ[(size_t)r0 * DD + c])       = v0;
            *(__half2*)(&g_bufZ[(size_t)(r0 + 8) * DD + c]) = v1;
        }
    }
}

// ---------------- SpMM gather (fp16 rows, fp32 accumulate, deg_j applied here) ----------------
__device__ __forceinline__ float2 h2f2(unsigned int u) {
    __half2 h = *reinterpret_cast<__half2*>(&u);
    return __half22float2(h);
}
__device__ __forceinline__ void acc8(float* a, uint4 q, float dj) {
    float2 f;
    f = h2f2(q.x); a[0] += dj * f.x; a[1] += dj * f.y;
    f = h2f2(q.y); a[2] += dj * f.x; a[3] += dj * f.y;
    f = h2f2(q.z); a[4] += dj * f.x; a[5] += dj * f.y;
    f = h2f2(q.w); a[6] += dj * f.x; a[7] += dj * f.y;
}

__global__ __launch_bounds__(256)
void spmm_gather(const float* __restrict__ bias, float* __restrict__ outp, int do_relu,
                 int rowOff) {
    int warp = (blockIdx.x * blockDim.x + threadIdx.x) >> 5;
    int lane = threadIdx.x & 31;
    if (warp >= HROWS) return;
    int row = rowOff + warp;
    int bbase = row & ~(NN - 1);

    const uint4* Z4 = (const uint4*)g_bufZ;

    float acc[16];
    #pragma unroll
    for (int q = 0; q < 16; q++) acc[q] = 0.0f;

    int cnt = g_cnt[row];
    const unsigned short* lst = &g_idx[(size_t)row * MAXD];
    #pragma unroll 2
    for (int k = 0; k < cnt; k++) {
        int j = lst[k];
        float dj = g_deg[bbase + j];
        const uint4* zr = Z4 + (size_t)(bbase + j) * (DD / 8);
        uint4 q0 = zr[lane];
        uint4 q1 = zr[lane + 32];
        acc8(acc, q0, dj);
        acc8(acc + 8, q1, dj);
    }

    float dv = g_deg[row];
    const float4* bv = (const float4*)bias;
    float o[16];
    #pragma unroll
    for (int h = 0; h < 2; h++) {
        float4 ba = bv[h * 64 + 2 * lane];
        float4 bb = bv[h * 64 + 2 * lane + 1];
        float* a = acc + h * 8;
        float* oo = o + h * 8;
        oo[0] = a[0] * dv + ba.x; oo[1] = a[1] * dv + ba.y;
        oo[2] = a[2] * dv + ba.z; oo[3] = a[3] * dv + ba.w;
        oo[4] = a[4] * dv + bb.x; oo[5] = a[5] * dv + bb.y;
        oo[6] = a[6] * dv + bb.z; oo[7] = a[7] * dv + bb.w;
    }
    if (do_relu) {
        #pragma unroll
        for (int q = 0; q < 16; q++) o[q] = fmaxf(o[q], 0.0f);
    }

    if (outp) {
        float4* ov = (float4*)(outp + (size_t)row * DD);
        #pragma unroll
        for (int h = 0; h < 2; h++) {
            ov[h * 64 + 2 * lane]     = make_float4(o[h*8+0], o[h*8+1], o[h*8+2], o[h*8+3]);
            ov[h * 64 + 2 * lane + 1] = make_float4(o[h*8+4], o[h*8+5], o[h*8+6], o[h*8+7]);
        }
    } else {
        uint4* hv = (uint4*)(g_bufH + (size_t)row * DD);
        #pragma unroll
        for (int h = 0; h < 2; h++) {
            uint4 u;
            __half2 p0 = __floats2half2_rn(o[h*8+0], o[h*8+1]);
            __half2 p1 = __floats2half2_rn(o[h*8+2], o[h*8+3]);
            __half2 p2 = __floats2half2_rn(o[h*8+4], o[h*8+5]);
            __half2 p3 = __floats2half2_rn(o[h*8+6], o[h*8+7]);
            u.x = *(unsigned int*)&p0; u.y = *(unsigned int*)&p1;
            u.z = *(unsigned int*)&p2; u.w = *(unsigned int*)&p3;
            hv[h * 32 + lane] = u;
        }
    }
}

// ---------------- launch: two batch-pair pipelines on two streams ----------------
extern "C" void kernel_launch(void* const* d_in, const int* in_sizes, int n_in,
                              void* d_out, int out_size) {
    const float* X   = (const float*)d_in[0];
    const float* adj = (const float*)d_in[1];
    const float* W1  = (const float*)d_in[2];
    const float* b1  = (const float*)d_in[3];
    const float* W2  = (const float*)d_in[4];
    const float* b2  = (const float*)d_in[5];
    const float* W3  = (const float*)d_in[6];
    const float* b3  = (const float*)d_in[7];
    float* out = (float*)d_out;

    static cudaStream_t s2 = nullptr;
    static cudaEvent_t evFork = nullptr, evBuild = nullptr, evCvt = nullptr, evDone = nullptr;
    static bool cfgDone = false;
    if (!s2) {
        cudaStreamCreateWithFlags(&s2, cudaStreamNonBlocking);
        cudaEventCreateWithFlags(&evFork, cudaEventDisableTiming);
        cudaEventCreateWithFlags(&evBuild, cudaEventDisableTiming);
        cudaEventCreateWithFlags(&evCvt, cudaEventDisableTiming);
        cudaEventCreateWithFlags(&evDone, cudaEventDisableTiming);
    }
    if (!cfgDone) {
        cudaFuncSetAttribute(gemm_f16, cudaFuncAttributeMaxDynamicSharedMemorySize, GEMM_SMEM);
        cfgDone = true;
    }

    dim3 ggrid(DD / BN, HROWS / BM);     // (4, 64) per pair
    int sgrid = HROWS * 32 / 256;        // 1024 per pair

    // fork: adjacency build on s2, cvt on main
    cudaEventRecord(evFork, 0);
    cudaStreamWaitEvent(s2, evFork, 0);
    build_seg<<<dim3(NN / 32, NB), dim3(32, SEGS), 0, s2>>>(adj);
    compact_deg<<<NROWS / 256, 256, 0, s2>>>();
    cudaEventRecord(evBuild, s2);

    cvt_w3<<<dim3((DD * DD + 255) / 256, 3), 256>>>(W1, W2, W3);
    cvt_x<<<(NROWS * DD / 4 + 255) / 256, 256>>>(X);
    cudaEventRecord(evCvt, 0);

    // ---- pair 0 chain on stream 0 ----
    gemm_f16<<<ggrid, 256, GEMM_SMEM>>>(0, 0);
    cudaStreamWaitEvent(0, evBuild, 0);
    spmm_gather<<<sgrid, 256>>>(b1, nullptr, 1, 0);
    gemm_f16<<<ggrid, 256, GEMM_SMEM>>>(1, 0);
    spmm_gather<<<sgrid, 256>>>(b2, nullptr, 1, 0);
    gemm_f16<<<ggrid, 256, GEMM_SMEM>>>(2, 0);
    spmm_gather<<<sgrid, 256>>>(b3, out, 0, 0);

    // ---- pair 1 chain on s2 (build already ordered on s2) ----
    cudaStreamWaitEvent(s2, evCvt, 0);
    gemm_f16<<<ggrid, 256, GEMM_SMEM, s2>>>(0, HROWS);
    spmm_gather<<<sgrid, 256, 0, s2>>>(b1, nullptr, 1, HROWS);
    gemm_f16<<<ggrid, 256, GEMM_SMEM, s2>>>(1, HROWS);
    spmm_gather<<<sgrid, 256, 0, s2>>>(b2, nullptr, 1, HROWS);
    gemm_f16<<<ggrid, 256, GEMM_SMEM, s2>>>(2, HROWS);
    spmm_gather<<<sgrid, 256, 0, s2>>>(b3, out, 0, HROWS);
    cudaEventRecord(evDone, s2);

    cudaStreamWaitEvent(0, evDone, 0);
}